// round 4
// baseline (speedup 1.0000x reference)
#include <cuda_runtime.h>
#include <math.h>

#define NSC 7
#define NB 8
#define ADIM 512
#define MAPSZ (NB * ADIM * ADIM)       // 2,097,152 cells per scale
#define TT 257                         // padded tiles per dim (514/2)
#define MAPF4 (TT * TT)                // 66049 float4 tiles per (map, replica)

// Scratch: 4 shift-replicas per scale, 2x2-tiled float4 grids. ~237 MB.
// INVARIANT: all-zero at entry to every kernel_launch call. __device__ globals
// are zero-initialized at module load; k_restore/k_final re-zero after use.
__device__ float4       g_rep[NSC][4][NB * MAPF4];
__device__ float        g_sumlog[NSC];
__device__ unsigned int g_max[NSC];     // float bits (values >= 0)
__device__ unsigned int g_nzero[NSC];
__device__ unsigned int g_npos;

// ---------------------------------------------------------------------------
// K1: bilinear scatter for one scale — ONE red.global.add.v4.f32 per point.
// Replica (sx,sy) holds logical (x,y) at stored (x+sx, y+sy); sx=ixf&1,
// sy=iyf&1 makes the 2x2 footprint exactly one aligned float4 tile.
// Grid-stride with a capped grid so stats/restore CTAs can co-schedule.
// ---------------------------------------------------------------------------
__device__ __forceinline__ void scat1(int s, int b, float r, float c) {
    float xf = fminf(fmaxf(floorf(r), 0.f), 511.f);
    float yf = fminf(fmaxf(floorf(c), 0.f), 511.f);
    float xw = r - xf;
    float yw = c - yf;
    int ix = (int)xf, iy = (int)yf;
    int sx = ix & 1, sy = iy & 1;
    float4* a = &g_rep[s][sx * 2 + sy][b * MAPF4 + ((ix + sx) >> 1) * TT + ((iy + sy) >> 1)];
    float wx0 = 1.f - xw, wy0 = 1.f - yw;
    // components: (dx,dy) = (0,0),(0,1),(1,0),(1,1) relative to (ixf,iyf)
    asm volatile("red.global.add.v4.f32 [%0], {%1, %2, %3, %4};"
                 :: "l"(a), "f"(wx0 * wy0), "f"(wx0 * yw),
                    "f"(xw * wy0), "f"(xw * yw)
                 : "memory");
}

__global__ void __launch_bounds__(256) k_scatter(
        const float4* __restrict__ r3, const float4* __restrict__ c3,
        const float4* __restrict__ r4, const float4* __restrict__ c4, int s) {
    const int off = s * (MAPSZ / 4);
    const int stride = gridDim.x * blockDim.x;
    for (int i = blockIdx.x * blockDim.x + threadIdx.x; i < MAPSZ / 4; i += stride) {
        int b = i >> 16;                             // batch within scale
        float4 rA = r3[off + i], cA = c3[off + i];
        float4 rB = r4[off + i], cB = c4[off + i];
        scat1(s, b, rA.x, cA.x); scat1(s, b, rA.y, cA.y);
        scat1(s, b, rA.z, cA.z); scat1(s, b, rA.w, cA.w);
        scat1(s, b, rB.x, cB.x); scat1(s, b, rB.y, cB.y);
        scat1(s, b, rB.z, cB.z); scat1(s, b, rB.w, cB.w);
    }
}

// ---------------------------------------------------------------------------
// K2: fused combine + max + masked log-stats for one scale (read-only).
// One thread per 2x2 logical block; combined dm values live in registers.
// BCE algebra: sum_{mask} min(lm - log(dm), 100)
//            = (npos - nzero)*lm - sum_{mask,dm>0} log(dm) + 100*nzero
// ---------------------------------------------------------------------------
__device__ __forceinline__ void stat_cell(float d, float t, float& sl,
                                          unsigned& nz, unsigned& np) {
    if (t == 1.0f) {
        np++;
        if (d == 0.f) nz++;
        else sl += logf(d);
    }
}

__global__ void __launch_bounds__(256) k_stats(const float* __restrict__ target, int s) {
    int id = blockIdx.x * blockDim.x + threadIdx.x;  // [0, NB*256*256)
    float mx = 0.f, sl = 0.f;
    unsigned nz = 0, np = 0;
    {
        int b   = id >> 16;
        int rem = id & 65535;
        int bx  = rem >> 8;
        int by  = rem & 255;
        int t00 = b * MAPF4 + bx * TT + by;

        const float4* __restrict__ r00 = &g_rep[s][0][0];
        const float4* __restrict__ r01 = &g_rep[s][1][0];
        const float4* __restrict__ r10 = &g_rep[s][2][0];
        const float4* __restrict__ r11 = &g_rep[s][3][0];

        // logical cells (2bx+dx, 2by+dy), accumulators c[dx][dy]
        float4 A = r00[t00];
        float c00 = A.x, c01 = A.y, c10 = A.z, c11 = A.w;

        float4 B0 = r01[t00], B1 = r01[t00 + 1];
        c00 += B0.y; c10 += B0.w; c01 += B1.x; c11 += B1.z;

        float4 C0 = r10[t00], C1 = r10[t00 + TT];
        c00 += C0.z; c01 += C0.w; c10 += C1.x; c11 += C1.y;

        float4 D00 = r11[t00],      D01 = r11[t00 + 1];
        float4 D10 = r11[t00 + TT], D11 = r11[t00 + TT + 1];
        c00 += D00.w; c01 += D01.z; c10 += D10.y; c11 += D11.x;

        mx = fmaxf(fmaxf(c00, c01), fmaxf(c10, c11));

        const float* tp = target + b * (ADIM * ADIM) + (2 * bx) * ADIM + 2 * by;
        float2 t0 = *(const float2*)tp;
        float2 t1 = *(const float2*)(tp + ADIM);
        stat_cell(c00, t0.x, sl, nz, np);
        stat_cell(c01, t0.y, sl, nz, np);
        stat_cell(c10, t1.x, sl, nz, np);
        stat_cell(c11, t1.y, sl, nz, np);
    }
    #pragma unroll
    for (int o = 16; o; o >>= 1) {
        mx = fmaxf(mx, __shfl_xor_sync(0xFFFFFFFFu, mx, o));
        sl += __shfl_xor_sync(0xFFFFFFFFu, sl, o);
        nz += __shfl_xor_sync(0xFFFFFFFFu, nz, o);
        np += __shfl_xor_sync(0xFFFFFFFFu, np, o);
    }
    __shared__ float    smx[8], ssl[8];
    __shared__ unsigned snz[8], snp[8];
    int w = threadIdx.x >> 5;
    if ((threadIdx.x & 31) == 0) { smx[w] = mx; ssl[w] = sl; snz[w] = nz; snp[w] = np; }
    __syncthreads();
    if (threadIdx.x == 0) {
        float bmx = smx[0], bsl = ssl[0];
        unsigned bnz = snz[0], bnp = snp[0];
        #pragma unroll
        for (int k = 1; k < 8; k++) {
            bmx = fmaxf(bmx, smx[k]); bsl += ssl[k]; bnz += snz[k]; bnp += snp[k];
        }
        atomicMax(&g_max[s], __float_as_uint(bmx));
        atomicAdd(&g_sumlog[s], bsl);
        if (bnz) atomicAdd(&g_nzero[s], bnz);
        if (s == 0) atomicAdd(&g_npos, bnp);
    }
}

// ---------------------------------------------------------------------------
// K2b: restore one scale's replicas to zero (runs AFTER stats(s); no
// downstream deps inside the run — overlaps the remaining scatter chain).
// ---------------------------------------------------------------------------
__global__ void __launch_bounds__(256) k_restore(int s) {
    const int n = 4 * NB * MAPF4;
    float4* p = &g_rep[s][0][0];
    const float4 z = make_float4(0.f, 0.f, 0.f, 0.f);
    const int stride = gridDim.x * blockDim.x;
    for (int j = blockIdx.x * blockDim.x + threadIdx.x; j < n; j += stride)
        p[j] = z;
}

// ---------------------------------------------------------------------------
// K3: final: total = sum_s ((npos-nzero_s)*log(max_s) - sumlog_s + 100*nzero_s)/npos
// Then restore scalar accumulators to zero (maintains the invariant).
// ---------------------------------------------------------------------------
__global__ void k_final(float* __restrict__ out) {
    float np = (float)g_npos;
    float tot = 0.f;
    #pragma unroll
    for (int i = 0; i < NSC; i++) {
        float lm = logf(__uint_as_float(g_max[i]));
        float nzf = (float)g_nzero[i];
        tot += ((np - nzf) * lm - g_sumlog[i] + 100.f * nzf) / np;
        g_sumlog[i] = 0.f; g_max[i] = 0u; g_nzero[i] = 0u;
    }
    g_npos = 0u;
    out[0] = tot;
}

// ---------------------------------------------------------------------------
// Launch: D: scatter(0..6) (capped grid, grid-stride) -> final
//         C: stats(s) <- scatter(s)        (overlaps scatter(s+1))
//         Z: restore(s) <- stats(s)        (overlaps remaining scatters)
// ---------------------------------------------------------------------------
static cudaStream_t sZ = nullptr, sC = nullptr;
static cudaEvent_t  evS[NSC], evT[NSC], evZdone, evCdone;

extern "C" void kernel_launch(void* const* d_in, const int* in_sizes, int n_in,
                              void* d_out, int out_size) {
    const float4* r3 = (const float4*)d_in[0];
    const float4* c3 = (const float4*)d_in[1];
    const float4* r4 = (const float4*)d_in[2];
    const float4* c4 = (const float4*)d_in[3];
    const float*  target = (const float*)d_in[4];
    float* out = (float*)d_out;

    if (!sZ) {  // one-time host-side resource creation (no device allocs)
        cudaStreamCreateWithFlags(&sZ, cudaStreamNonBlocking);
        cudaStreamCreateWithFlags(&sC, cudaStreamNonBlocking);
        cudaEventCreateWithFlags(&evZdone, cudaEventDisableTiming);
        cudaEventCreateWithFlags(&evCdone, cudaEventDisableTiming);
        for (int i = 0; i < NSC; i++) {
            cudaEventCreateWithFlags(&evS[i], cudaEventDisableTiming);
            cudaEventCreateWithFlags(&evT[i], cudaEventDisableTiming);
        }
    }
    cudaStream_t D = 0;

    const int SC_GRID = 760;    // ~5 CTAs/SM: leave SM headroom for stats/restore
    const int ST_GRID = 2048;   // one thread per 2x2 logical block
    const int RЗ_GRID = 1024;

    for (int s = 0; s < NSC; s++) {
        k_scatter<<<SC_GRID, 256, 0, D>>>(r3, c3, r4, c4, s);
        cudaEventRecord(evS[s], D);
        cudaStreamWaitEvent(sC, evS[s], 0);
        k_stats<<<ST_GRID, 256, 0, sC>>>(target, s);
        cudaEventRecord(evT[s], sC);
        cudaStreamWaitEvent(sZ, evT[s], 0);
        k_restore<<<RЗ_GRID, 256, 0, sZ>>>(s);
    }
    cudaEventRecord(evCdone, sC);
    cudaEventRecord(evZdone, sZ);

    cudaStreamWaitEvent(D, evCdone, 0);
    k_final<<<1, 1, 0, D>>>(out);
    cudaStreamWaitEvent(D, evZdone, 0);   // graph end also waits on restores
}

// round 5
// speedup vs baseline: 1.0135x; 1.0135x over previous
#include <cuda_runtime.h>
#include <math.h>

#define NSC 7
#define NB 8
#define ADIM 512
#define MAPSZ (NB * ADIM * ADIM)       // 2,097,152 cells per scale
#define PTS (NSC * MAPSZ)              // 14,680,064 points per coord set
#define TT 257                         // padded tiles per dim (514/2)
#define MAPF4 (TT * TT)                // 66049 float4 tiles per (map, replica)

// Scratch: 4 shift-replicas per scale, 2x2-tiled float4 grids. ~237 MB.
// INVARIANT: all-zero at entry to every kernel_launch call. __device__ globals
// are zero-initialized at module load; k_restore/k_final re-zero after use.
__device__ float4       g_rep[NSC][4][NB * MAPF4];
__device__ float        g_sumlog[NSC];
__device__ unsigned int g_max[NSC];     // float bits (values >= 0)
__device__ unsigned int g_nzero[NSC];
__device__ unsigned int g_npos;

// ---------------------------------------------------------------------------
// K1: bilinear scatter, ALL scales, full grid — ONE red.global.add.v4.f32 per
// point. Replica (sx,sy) holds logical (x,y) at stored (x+sx, y+sy); with
// sx=ixf&1, sy=iyf&1 the 2x2 footprint is exactly one aligned float4 tile.
// ---------------------------------------------------------------------------
__device__ __forceinline__ void scat1(int s, int b, float r, float c) {
    float xf = fminf(fmaxf(floorf(r), 0.f), 511.f);
    float yf = fminf(fmaxf(floorf(c), 0.f), 511.f);
    float xw = r - xf;
    float yw = c - yf;
    int ix = (int)xf, iy = (int)yf;
    int sx = ix & 1, sy = iy & 1;
    float4* a = &g_rep[s][sx * 2 + sy][b * MAPF4 + ((ix + sx) >> 1) * TT + ((iy + sy) >> 1)];
    float wx0 = 1.f - xw, wy0 = 1.f - yw;
    // components: (dx,dy) = (0,0),(0,1),(1,0),(1,1) relative to (ixf,iyf)
    asm volatile("red.global.add.v4.f32 [%0], {%1, %2, %3, %4};"
                 :: "l"(a), "f"(wx0 * wy0), "f"(wx0 * yw),
                    "f"(xw * wy0), "f"(xw * yw)
                 : "memory");
}

__global__ void __launch_bounds__(256) k_scatter(
        const float4* __restrict__ r3, const float4* __restrict__ c3,
        const float4* __restrict__ r4, const float4* __restrict__ c4) {
    int i = blockIdx.x * blockDim.x + threadIdx.x;   // [0, PTS/4)
    if (i >= PTS / 4) return;
    int s = i >> 19;                                 // scale (MAPSZ/4 = 2^19)
    int b = (i >> 16) & 7;                           // batch within scale

    float4 rA = r3[i], cA = c3[i];
    float4 rB = r4[i], cB = c4[i];
    scat1(s, b, rA.x, cA.x); scat1(s, b, rA.y, cA.y);
    scat1(s, b, rA.z, cA.z); scat1(s, b, rA.w, cA.w);
    scat1(s, b, rB.x, cB.x); scat1(s, b, rB.y, cB.y);
    scat1(s, b, rB.z, cB.z); scat1(s, b, rB.w, cB.w);
}

// ---------------------------------------------------------------------------
// K2: fused combine + max + masked log-stats for one scale (read-only).
// One thread per 2x2 logical block; combined dm values live in registers.
// BCE algebra: sum_{mask} min(lm - log(dm), 100)
//            = (npos - nzero)*lm - sum_{mask,dm>0} log(dm) + 100*nzero
// (clamp engages only at dm==0: any nonzero dm gives lm-log(dm) << 100)
// ---------------------------------------------------------------------------
__device__ __forceinline__ void stat_cell(float d, float t, float& sl,
                                          unsigned& nz, unsigned& np) {
    if (t == 1.0f) {
        np++;
        if (d == 0.f) nz++;
        else sl += logf(d);
    }
}

__global__ void __launch_bounds__(256) k_stats(const float* __restrict__ target, int s) {
    int id = blockIdx.x * blockDim.x + threadIdx.x;  // [0, NB*256*256)
    float mx = 0.f, sl = 0.f;
    unsigned nz = 0, np = 0;
    {
        int b   = id >> 16;
        int rem = id & 65535;
        int bx  = rem >> 8;
        int by  = rem & 255;
        int t00 = b * MAPF4 + bx * TT + by;

        const float4* __restrict__ r00 = &g_rep[s][0][0];
        const float4* __restrict__ r01 = &g_rep[s][1][0];
        const float4* __restrict__ r10 = &g_rep[s][2][0];
        const float4* __restrict__ r11 = &g_rep[s][3][0];

        // logical cells (2bx+dx, 2by+dy), accumulators c[dx][dy]
        float4 A = r00[t00];
        float c00 = A.x, c01 = A.y, c10 = A.z, c11 = A.w;

        float4 B0 = r01[t00], B1 = r01[t00 + 1];
        c00 += B0.y; c10 += B0.w; c01 += B1.x; c11 += B1.z;

        float4 C0 = r10[t00], C1 = r10[t00 + TT];
        c00 += C0.z; c01 += C0.w; c10 += C1.x; c11 += C1.y;

        float4 D00 = r11[t00],      D01 = r11[t00 + 1];
        float4 D10 = r11[t00 + TT], D11 = r11[t00 + TT + 1];
        c00 += D00.w; c01 += D01.z; c10 += D10.y; c11 += D11.x;

        mx = fmaxf(fmaxf(c00, c01), fmaxf(c10, c11));

        const float* tp = target + b * (ADIM * ADIM) + (2 * bx) * ADIM + 2 * by;
        float2 t0 = *(const float2*)tp;
        float2 t1 = *(const float2*)(tp + ADIM);
        stat_cell(c00, t0.x, sl, nz, np);
        stat_cell(c01, t0.y, sl, nz, np);
        stat_cell(c10, t1.x, sl, nz, np);
        stat_cell(c11, t1.y, sl, nz, np);
    }
    #pragma unroll
    for (int o = 16; o; o >>= 1) {
        mx = fmaxf(mx, __shfl_xor_sync(0xFFFFFFFFu, mx, o));
        sl += __shfl_xor_sync(0xFFFFFFFFu, sl, o);
        nz += __shfl_xor_sync(0xFFFFFFFFu, nz, o);
        np += __shfl_xor_sync(0xFFFFFFFFu, np, o);
    }
    __shared__ float    smx[8], ssl[8];
    __shared__ unsigned snz[8], snp[8];
    int w = threadIdx.x >> 5;
    if ((threadIdx.x & 31) == 0) { smx[w] = mx; ssl[w] = sl; snz[w] = nz; snp[w] = np; }
    __syncthreads();
    if (threadIdx.x == 0) {
        float bmx = smx[0], bsl = ssl[0];
        unsigned bnz = snz[0], bnp = snp[0];
        #pragma unroll
        for (int k = 1; k < 8; k++) {
            bmx = fmaxf(bmx, smx[k]); bsl += ssl[k]; bnz += snz[k]; bnp += snp[k];
        }
        atomicMax(&g_max[s], __float_as_uint(bmx));
        atomicAdd(&g_sumlog[s], bsl);
        if (bnz) atomicAdd(&g_nzero[s], bnz);
        if (s == 0) atomicAdd(&g_npos, bnp);
    }
}

// ---------------------------------------------------------------------------
// K2b: restore one scale's replicas to zero. Runs immediately after k_stats(s)
// so the 33.8 MB working set is still L2-resident -> writes are L2 hits.
// ---------------------------------------------------------------------------
__global__ void __launch_bounds__(256) k_restore(int s) {
    const int n = 4 * NB * MAPF4;
    float4* p = &g_rep[s][0][0];
    const float4 z = make_float4(0.f, 0.f, 0.f, 0.f);
    const int stride = gridDim.x * blockDim.x;
    for (int j = blockIdx.x * blockDim.x + threadIdx.x; j < n; j += stride)
        p[j] = z;
}

// ---------------------------------------------------------------------------
// K3: final: total = sum_s ((npos-nzero_s)*log(max_s) - sumlog_s + 100*nzero_s)/npos
// Then restore scalar accumulators to zero (maintains the invariant).
// ---------------------------------------------------------------------------
__global__ void k_final(float* __restrict__ out) {
    float np = (float)g_npos;
    float tot = 0.f;
    #pragma unroll
    for (int i = 0; i < NSC; i++) {
        float lm = logf(__uint_as_float(g_max[i]));
        float nzf = (float)g_nzero[i];
        tot += ((np - nzf) * lm - g_sumlog[i] + 100.f * nzf) / np;
        g_sumlog[i] = 0.f; g_max[i] = 0u; g_nzero[i] = 0u;
    }
    g_npos = 0u;
    out[0] = tot;
}

// ---------------------------------------------------------------------------
// Launch: single stream, serial. scatter(all) -> [stats(s); restore(s)] x7 -> final
// ---------------------------------------------------------------------------
extern "C" void kernel_launch(void* const* d_in, const int* in_sizes, int n_in,
                              void* d_out, int out_size) {
    const float4* r3 = (const float4*)d_in[0];
    const float4* c3 = (const float4*)d_in[1];
    const float4* r4 = (const float4*)d_in[2];
    const float4* c4 = (const float4*)d_in[3];
    const float*  target = (const float*)d_in[4];
    float* out = (float*)d_out;

    k_scatter<<<PTS / 4 / 256, 256>>>(r3, c3, r4, c4);   // 14336 CTAs
    for (int s = 0; s < NSC; s++) {
        k_stats<<<2048, 256>>>(target, s);
        k_restore<<<2048, 256>>>(s);
    }
    k_final<<<1, 1>>>(out);
}

// round 6
// speedup vs baseline: 1.4921x; 1.4722x over previous
#include <cuda_runtime.h>
#include <cuda_fp16.h>
#include <math.h>

#define NSC 7
#define NB 8
#define ADIM 512
#define MAPSZ (NB * ADIM * ADIM)       // 2,097,152 cells per scale
#define PTS (NSC * MAPSZ)              // 14,680,064 points per coord set
#define TT 257                         // padded tiles per dim (514/2)
#define MAPH (TT * TT)                 // 66049 8-byte tiles per (map, replica)

// Scratch: 4 shift-replicas per scale; each 2x2 logical tile = 4 x f16 = uint2.
// ~118 MB total. INVARIANT: all-zero at entry to every kernel_launch call
// (__device__ globals zero-init at load; k_restore/k_final re-zero after use).
__device__ uint2        g_rep[NSC][4][NB * MAPH];
__device__ float        g_sumlog[NSC];
__device__ unsigned int g_max[NSC];     // float bits (values >= 0)
__device__ unsigned int g_nzero[NSC];
__device__ unsigned int g_npos;

// ---------------------------------------------------------------------------
// K1: bilinear scatter, ALL scales — ONE red.global.add.noftz.v2.f16x2 per
// point (8 bytes). Replica (sx,sy) stores logical (x,y) at (x+sx, y+sy);
// sx=ixf&1, sy=iyf&1 puts the 2x2 footprint in exactly one aligned tile.
// Tile layout: halves [0..3] = (dx,dy) = (0,0),(0,1),(1,0),(1,1).
// ---------------------------------------------------------------------------
__device__ __forceinline__ void scat1(int s, int b, float r, float c) {
    float xf = fminf(fmaxf(floorf(r), 0.f), 511.f);
    float yf = fminf(fmaxf(floorf(c), 0.f), 511.f);
    float xw = r - xf;
    float yw = c - yf;
    int ix = (int)xf, iy = (int)yf;
    int sx = ix & 1, sy = iy & 1;
    uint2* a = &g_rep[s][sx * 2 + sy][b * MAPH + ((ix + sx) >> 1) * TT + ((iy + sy) >> 1)];
    float wx0 = 1.f - xw, wy0 = 1.f - yw;
    __half2 lo = __floats2half2_rn(wx0 * wy0, wx0 * yw);   // (0,0),(0,1)
    __half2 hi = __floats2half2_rn(xw * wy0,  xw * yw);    // (1,0),(1,1)
    unsigned ulo = *reinterpret_cast<unsigned*>(&lo);
    unsigned uhi = *reinterpret_cast<unsigned*>(&hi);
    asm volatile("red.global.add.noftz.v2.f16x2 [%0], {%1, %2};"
                 :: "l"(a), "r"(ulo), "r"(uhi)
                 : "memory");
}

__global__ void __launch_bounds__(256) k_scatter(
        const float4* __restrict__ r3, const float4* __restrict__ c3,
        const float4* __restrict__ r4, const float4* __restrict__ c4) {
    int i = blockIdx.x * blockDim.x + threadIdx.x;   // [0, PTS/4)
    if (i >= PTS / 4) return;
    int s = i >> 19;                                 // scale (MAPSZ/4 = 2^19)
    int b = (i >> 16) & 7;                           // batch within scale

    float4 rA = r3[i], cA = c3[i];
    float4 rB = r4[i], cB = c4[i];
    scat1(s, b, rA.x, cA.x); scat1(s, b, rA.y, cA.y);
    scat1(s, b, rA.z, cA.z); scat1(s, b, rA.w, cA.w);
    scat1(s, b, rB.x, cB.x); scat1(s, b, rB.y, cB.y);
    scat1(s, b, rB.z, cB.z); scat1(s, b, rB.w, cB.w);
}

// ---------------------------------------------------------------------------
// K2: fused combine + max + masked log-stats, ALL scales, one launch.
// One thread per 2x2 logical block. BCE algebra:
//   sum_{mask} min(lm - log(dm), 100)
//     = (npos - nzero)*lm - sum_{mask,dm>0} log(dm) + 100*nzero
// ---------------------------------------------------------------------------
__device__ __forceinline__ void stat_cell(float d, float t, float& sl,
                                          unsigned& nz, unsigned& np) {
    if (t == 1.0f) {
        np++;
        if (d == 0.f) nz++;
        else sl += logf(d);
    }
}

__device__ __forceinline__ float2 h2f(unsigned u) {
    __half2 h = *reinterpret_cast<__half2*>(&u);
    return __half22float2(h);
}

__global__ void __launch_bounds__(256) k_stats(const float* __restrict__ target) {
    int id = blockIdx.x * blockDim.x + threadIdx.x;  // [0, NSC*NB*256*256)
    const int s   = id >> 19;
    const int rem = id & ((1 << 19) - 1);
    float mx = 0.f, sl = 0.f;
    unsigned nz = 0, np = 0;
    {
        int b   = rem >> 16;
        int bx  = (rem >> 8) & 255;
        int by  = rem & 255;
        int t00 = b * MAPH + bx * TT + by;

        const uint2* __restrict__ r00 = g_rep[s][0];
        const uint2* __restrict__ r01 = g_rep[s][1];
        const uint2* __restrict__ r10 = g_rep[s][2];
        const uint2* __restrict__ r11 = g_rep[s][3];

        // logical cells (2bx+dx, 2by+dy); accumulators c[dx][dy]
        uint2 A = r00[t00];
        float2 Al = h2f(A.x), Ah = h2f(A.y);
        float c00 = Al.x, c01 = Al.y, c10 = Ah.x, c11 = Ah.y;

        uint2 B0 = r01[t00], B1 = r01[t00 + 1];
        c00 += h2f(B0.x).y;  c10 += h2f(B0.y).y;    // offsets 1, 3
        c01 += h2f(B1.x).x;  c11 += h2f(B1.y).x;    // offsets 0, 2

        uint2 C0 = r10[t00], C1 = r10[t00 + TT];
        { float2 v = h2f(C0.y); c00 += v.x; c01 += v.y; }   // offsets 2, 3
        { float2 v = h2f(C1.x); c10 += v.x; c11 += v.y; }   // offsets 0, 1

        uint2 D00 = r11[t00],      D01 = r11[t00 + 1];
        uint2 D10 = r11[t00 + TT], D11 = r11[t00 + TT + 1];
        c00 += h2f(D00.y).y;   // offset 3
        c01 += h2f(D01.y).x;   // offset 2
        c10 += h2f(D10.x).y;   // offset 1
        c11 += h2f(D11.x).x;   // offset 0

        mx = fmaxf(fmaxf(c00, c01), fmaxf(c10, c11));

        const float* tp = target + b * (ADIM * ADIM) + (2 * bx) * ADIM + 2 * by;
        float2 t0 = *(const float2*)tp;
        float2 t1 = *(const float2*)(tp + ADIM);
        stat_cell(c00, t0.x, sl, nz, np);
        stat_cell(c01, t0.y, sl, nz, np);
        stat_cell(c10, t1.x, sl, nz, np);
        stat_cell(c11, t1.y, sl, nz, np);
    }
    #pragma unroll
    for (int o = 16; o; o >>= 1) {
        mx = fmaxf(mx, __shfl_xor_sync(0xFFFFFFFFu, mx, o));
        sl += __shfl_xor_sync(0xFFFFFFFFu, sl, o);
        nz += __shfl_xor_sync(0xFFFFFFFFu, nz, o);
        np += __shfl_xor_sync(0xFFFFFFFFu, np, o);
    }
    __shared__ float    smx[8], ssl[8];
    __shared__ unsigned snz[8], snp[8];
    int w = threadIdx.x >> 5;
    if ((threadIdx.x & 31) == 0) { smx[w] = mx; ssl[w] = sl; snz[w] = nz; snp[w] = np; }
    __syncthreads();
    if (threadIdx.x == 0) {
        // all threads of a CTA share the same s (65536 ids per (s,b))
        float bmx = smx[0], bsl = ssl[0];
        unsigned bnz = snz[0], bnp = snp[0];
        #pragma unroll
        for (int k = 1; k < 8; k++) {
            bmx = fmaxf(bmx, smx[k]); bsl += ssl[k]; bnz += snz[k]; bnp += snp[k];
        }
        atomicMax(&g_max[s], __float_as_uint(bmx));
        atomicAdd(&g_sumlog[s], bsl);
        if (bnz) atomicAdd(&g_nzero[s], bnz);
        if (s == 0) atomicAdd(&g_npos, bnp);
    }
}

// ---------------------------------------------------------------------------
// K2b: restore ALL replicas to zero (single streaming-write launch, ~118 MB).
// ---------------------------------------------------------------------------
#define REP_U4 (NSC * 4 * NB * MAPH / 2)   // uint2 count / 2 = uint4 count
__global__ void __launch_bounds__(256) k_restore() {
    uint4* p = reinterpret_cast<uint4*>(&g_rep[0][0][0]);
    int j = blockIdx.x * blockDim.x + threadIdx.x;
    if (j < REP_U4) p[j] = make_uint4(0u, 0u, 0u, 0u);
}

// ---------------------------------------------------------------------------
// K3: final: total = sum_s ((npos-nzero_s)*log(max_s) - sumlog_s + 100*nzero_s)/npos
// Then restore scalar accumulators (maintains the zero invariant).
// ---------------------------------------------------------------------------
__global__ void k_final(float* __restrict__ out) {
    float np = (float)g_npos;
    float tot = 0.f;
    #pragma unroll
    for (int i = 0; i < NSC; i++) {
        float lm = logf(__uint_as_float(g_max[i]));
        float nzf = (float)g_nzero[i];
        tot += ((np - nzf) * lm - g_sumlog[i] + 100.f * nzf) / np;
        g_sumlog[i] = 0.f; g_max[i] = 0u; g_nzero[i] = 0u;
    }
    g_npos = 0u;
    out[0] = tot;
}

// ---------------------------------------------------------------------------
// Launch: single stream, 4 nodes: scatter -> stats(all) -> restore -> final
// ---------------------------------------------------------------------------
extern "C" void kernel_launch(void* const* d_in, const int* in_sizes, int n_in,
                              void* d_out, int out_size) {
    const float4* r3 = (const float4*)d_in[0];
    const float4* c3 = (const float4*)d_in[1];
    const float4* r4 = (const float4*)d_in[2];
    const float4* c4 = (const float4*)d_in[3];
    const float*  target = (const float*)d_in[4];
    float* out = (float*)d_out;

    k_scatter<<<PTS / 4 / 256, 256>>>(r3, c3, r4, c4);        // 14336 CTAs
    k_stats<<<NSC * NB * 256 * 256 / 256, 256>>>(target);     // 14336 CTAs
    k_restore<<<(REP_U4 + 255) / 256, 256>>>();
    k_final<<<1, 1>>>(out);
}

// round 7
// speedup vs baseline: 1.5490x; 1.0382x over previous
#include <cuda_runtime.h>
#include <cuda_fp16.h>
#include <math.h>

#define NSC 7
#define NB 8
#define ADIM 512
#define MAPSZ (NB * ADIM * ADIM)       // 2,097,152 cells per scale
#define PTS (NSC * MAPSZ)              // 14,680,064 points per coord set
#define TTY 258                        // tile-row stride (padded even for uint4)
#define TTX 257                        // tile rows
#define MAPH (TTX * TTY)               // 66306 tiles (8B each) per (map, replica)

// Scratch: 4 shift-replicas per scale; each 2x2 logical tile = 4 x f16 = uint2.
// ~119 MB. INVARIANT: all-zero at entry to every kernel_launch call
// (__device__ globals zero-init at load; k_restore_final re-zeroes after use).
__device__ __align__(16) uint2 g_rep[NSC][4][NB * MAPH];
__device__ float        g_sumlog[NSC];
__device__ unsigned int g_max[NSC];     // float bits (values >= 0)
__device__ unsigned int g_nzero[NSC];
__device__ unsigned int g_npos;
__device__ unsigned int g_ticket;       // last-block ticket (wraps back to 0)

// ---------------------------------------------------------------------------
// K1: bilinear scatter, ALL scales — ONE red.global.add.noftz.v2.f16x2 per
// point (8 bytes). Replica (sx,sy) stores logical (x,y) at (x+sx, y+sy);
// sx=ixf&1, sy=iyf&1 puts the 2x2 footprint in exactly one aligned tile.
// Tile halves [0..3] = (dx,dy) = (0,0),(0,1),(1,0),(1,1).
// ---------------------------------------------------------------------------
__device__ __forceinline__ void scat1(int s, int b, float r, float c) {
    float xf = fminf(fmaxf(floorf(r), 0.f), 511.f);
    float yf = fminf(fmaxf(floorf(c), 0.f), 511.f);
    float xw = r - xf;
    float yw = c - yf;
    int ix = (int)xf, iy = (int)yf;
    int sx = ix & 1, sy = iy & 1;
    uint2* a = &g_rep[s][sx * 2 + sy][b * MAPH + ((ix + sx) >> 1) * TTY + ((iy + sy) >> 1)];
    float wx0 = 1.f - xw, wy0 = 1.f - yw;
    __half2 lo = __floats2half2_rn(wx0 * wy0, wx0 * yw);   // (0,0),(0,1)
    __half2 hi = __floats2half2_rn(xw * wy0,  xw * yw);    // (1,0),(1,1)
    unsigned ulo = *reinterpret_cast<unsigned*>(&lo);
    unsigned uhi = *reinterpret_cast<unsigned*>(&hi);
    asm volatile("red.global.add.noftz.v2.f16x2 [%0], {%1, %2};"
                 :: "l"(a), "r"(ulo), "r"(uhi)
                 : "memory");
}

__global__ void __launch_bounds__(256) k_scatter(
        const float4* __restrict__ r3, const float4* __restrict__ c3,
        const float4* __restrict__ r4, const float4* __restrict__ c4) {
    int i = blockIdx.x * blockDim.x + threadIdx.x;   // [0, PTS/4)
    if (i >= PTS / 4) return;
    int s = i >> 19;                                 // scale (MAPSZ/4 = 2^19)
    int b = (i >> 16) & 7;                           // batch within scale

    float4 rA = r3[i], cA = c3[i];
    float4 rB = r4[i], cB = c4[i];
    scat1(s, b, rA.x, cA.x); scat1(s, b, rA.y, cA.y);
    scat1(s, b, rA.z, cA.z); scat1(s, b, rA.w, cA.w);
    scat1(s, b, rB.x, cB.x); scat1(s, b, rB.y, cB.y);
    scat1(s, b, rB.z, cB.z); scat1(s, b, rB.w, cB.w);
}

// ---------------------------------------------------------------------------
// K2: fused combine + max + masked log-stats, ALL scales, one launch.
// Each thread handles TWO adjacent home tiles (8 logical cells) with uint4
// loads. BCE algebra: sum_{mask} min(lm - log(dm), 100)
//   = (npos - nzero)*lm - sum_{mask,dm>0} log(dm) + 100*nzero
// ---------------------------------------------------------------------------
__device__ __forceinline__ float lohalf(unsigned u) { return __half2float(__ushort_as_half((unsigned short)(u & 0xFFFF))); }
__device__ __forceinline__ float hihalf(unsigned u) { return __half2float(__ushort_as_half((unsigned short)(u >> 16))); }

__device__ __forceinline__ void stat_cell(float d, float t, float& sl,
                                          unsigned& nz, unsigned& np) {
    if (t == 1.0f) {
        np++;
        if (d == 0.f) nz++;
        else sl += logf(d);
    }
}

__global__ void __launch_bounds__(256) k_stats(const float* __restrict__ target) {
    int id = blockIdx.x * blockDim.x + threadIdx.x;  // [0, NSC*NB*256*128)
    const int s   = id >> 18;
    const int rem = id & ((1 << 18) - 1);
    float mx = 0.f, sl = 0.f;
    unsigned nz = 0, np = 0;
    {
        int b   = rem >> 15;
        int bx  = (rem >> 7) & 255;
        int by  = (rem & 127) * 2;                   // even home-tile column
        int t00 = b * MAPH + bx * TTY + by;          // even -> 16B aligned

        const uint2* __restrict__ r00 = g_rep[s][0];
        const uint2* __restrict__ r01 = g_rep[s][1];
        const uint2* __restrict__ r10 = g_rep[s][2];
        const uint2* __restrict__ r11 = g_rep[s][3];

        uint4 A  = *(const uint4*)(r00 + t00);             // tiles t, t+1
        uint4 B0 = *(const uint4*)(r01 + t00);             // tiles t, t+1
        uint2 B2 = r01[t00 + 2];
        uint4 C0 = *(const uint4*)(r10 + t00);             // tiles t, t+1
        uint4 C1 = *(const uint4*)(r10 + t00 + TTY);       // tiles t+TTY, +1
        uint4 D0 = *(const uint4*)(r11 + t00);
        uint2 D2 = r11[t00 + 2];
        uint4 D1 = *(const uint4*)(r11 + t00 + TTY);
        uint2 D3 = r11[t00 + TTY + 2];

        // ---- home tile 0: logical block (bx, by) ----
        float a00 = lohalf(A.x) + hihalf(B0.x) + lohalf(C0.y) + hihalf(D0.y);
        float a01 = hihalf(A.x) + lohalf(B0.z) + hihalf(C0.y) + lohalf(D0.w);
        float a10 = lohalf(A.y) + hihalf(B0.y) + lohalf(C1.x) + hihalf(D1.x);
        float a11 = hihalf(A.y) + lohalf(B0.w) + hihalf(C1.x) + lohalf(D1.z);
        // ---- home tile 1: logical block (bx, by+1) ----
        float e00 = lohalf(A.z) + hihalf(B0.z) + lohalf(C0.w) + hihalf(D0.w);
        float e01 = hihalf(A.z) + lohalf(B2.x) + hihalf(C0.w) + lohalf(D2.y);
        float e10 = lohalf(A.w) + hihalf(B0.w) + lohalf(C1.z) + hihalf(D1.z);
        float e11 = hihalf(A.w) + lohalf(B2.y) + hihalf(C1.z) + lohalf(D3.x);

        mx = fmaxf(fmaxf(fmaxf(a00, a01), fmaxf(a10, a11)),
                   fmaxf(fmaxf(e00, e01), fmaxf(e10, e11)));

        // target: rows 2bx, 2bx+1; cols 2by..2by+3 (2by % 4 == 0 -> aligned)
        const float* tp = target + b * (ADIM * ADIM) + (2 * bx) * ADIM + 2 * by;
        float4 t0 = *(const float4*)tp;
        float4 t1 = *(const float4*)(tp + ADIM);
        stat_cell(a00, t0.x, sl, nz, np);
        stat_cell(a01, t0.y, sl, nz, np);
        stat_cell(e00, t0.z, sl, nz, np);
        stat_cell(e01, t0.w, sl, nz, np);
        stat_cell(a10, t1.x, sl, nz, np);
        stat_cell(a11, t1.y, sl, nz, np);
        stat_cell(e10, t1.z, sl, nz, np);
        stat_cell(e11, t1.w, sl, nz, np);
    }
    #pragma unroll
    for (int o = 16; o; o >>= 1) {
        mx = fmaxf(mx, __shfl_xor_sync(0xFFFFFFFFu, mx, o));
        sl += __shfl_xor_sync(0xFFFFFFFFu, sl, o);
        nz += __shfl_xor_sync(0xFFFFFFFFu, nz, o);
        np += __shfl_xor_sync(0xFFFFFFFFu, np, o);
    }
    __shared__ float    smx[8], ssl[8];
    __shared__ unsigned snz[8], snp[8];
    int w = threadIdx.x >> 5;
    if ((threadIdx.x & 31) == 0) { smx[w] = mx; ssl[w] = sl; snz[w] = nz; snp[w] = np; }
    __syncthreads();
    if (threadIdx.x == 0) {   // whole CTA shares one s (32768 ids per (s,b))
        float bmx = smx[0], bsl = ssl[0];
        unsigned bnz = snz[0], bnp = snp[0];
        #pragma unroll
        for (int k = 1; k < 8; k++) {
            bmx = fmaxf(bmx, smx[k]); bsl += ssl[k]; bnz += snz[k]; bnp += snp[k];
        }
        atomicMax(&g_max[s], __float_as_uint(bmx));
        atomicAdd(&g_sumlog[s], bsl);
        if (bnz) atomicAdd(&g_nzero[s], bnz);
        if (s == 0) atomicAdd(&g_npos, bnp);
    }
}

// ---------------------------------------------------------------------------
// K3: restore all replicas to zero; the LAST CTA (ticket) computes the final
// loss and resets the scalar accumulators (zero-invariant).
//   total = sum_s ((npos-nzero_s)*log(max_s) - sumlog_s + 100*nzero_s) / npos
// ---------------------------------------------------------------------------
#define REP_U4 (NSC * 4 * NB * MAPH / 2)
__global__ void __launch_bounds__(256) k_restore_final(float* __restrict__ out) {
    uint4* p = reinterpret_cast<uint4*>(&g_rep[0][0][0]);
    const uint4 z = make_uint4(0u, 0u, 0u, 0u);
    const int stride = gridDim.x * blockDim.x;
    for (int j = blockIdx.x * blockDim.x + threadIdx.x; j < REP_U4; j += stride)
        p[j] = z;
    __syncthreads();
    if (threadIdx.x == 0) {
        unsigned t = atomicInc(&g_ticket, gridDim.x - 1);  // wraps to 0 at last
        if (t == gridDim.x - 1) {
            // stats kernel completed before this launch; accumulators final.
            float np = (float)g_npos;
            float tot = 0.f;
            #pragma unroll
            for (int i = 0; i < NSC; i++) {
                float lm = logf(__uint_as_float(g_max[i]));
                float nzf = (float)g_nzero[i];
                tot += ((np - nzf) * lm - g_sumlog[i] + 100.f * nzf) / np;
                g_sumlog[i] = 0.f; g_max[i] = 0u; g_nzero[i] = 0u;
            }
            g_npos = 0u;
            out[0] = tot;
        }
    }
}

// ---------------------------------------------------------------------------
// Launch: single stream, 3 nodes: scatter -> stats -> restore+final
// ---------------------------------------------------------------------------
extern "C" void kernel_launch(void* const* d_in, const int* in_sizes, int n_in,
                              void* d_out, int out_size) {
    const float4* r3 = (const float4*)d_in[0];
    const float4* c3 = (const float4*)d_in[1];
    const float4* r4 = (const float4*)d_in[2];
    const float4* c4 = (const float4*)d_in[3];
    const float*  target = (const float*)d_in[4];
    float* out = (float*)d_out;

    k_scatter<<<PTS / 4 / 256, 256>>>(r3, c3, r4, c4);         // 14336 CTAs
    k_stats<<<NSC * NB * 256 * 128 / 256, 256>>>(target);      // 7168 CTAs
    k_restore_final<<<4096, 256>>>(out);
}